// round 14
// baseline (speedup 1.0000x reference)
#include <cuda_runtime.h>

#define SDIM 1024
#define DDIM 64
#define BH   16
#define NF   4
#define R2   4   // rows per conv/softmax block
#define KSPL 4   // k-splits for AV

typedef unsigned long long ull;

// d = a*b + d on packed f32x2
#define FMA2(d, a, b) asm("fma.rn.f32x2 %0, %1, %2, %0;" : "+l"(d) : "l"(a), "l"(b))
#define PACK_DUP(d, f) asm("mov.b64 %0, {%1, %1};" : "=l"(d) : "f"(f))
#define UNPACK2(lo, hi, v) asm("mov.b64 {%0, %1}, %2;" : "=f"(lo), "=f"(hi) : "l"(v))

// Scratch: dp scores / (later) AV partials, and attention probabilities.
__device__ float g_dp[(size_t)BH * SDIM * SDIM];    // 64 MB; reused as AV partials after K2
__device__ float g_attn[(size_t)BH * SDIM * SDIM];  // 64 MB

#define AS_STR 132   // 128 + 4 pad
#define BS_STR 68    // 64 + 4 pad

// ---------------------------------------------------------------------------
// K1: dp = (1/8) Q K^T.  128(s)x64(t) tile, 256 thr, 8s x 4t, f32x2. (60.4us)
// ---------------------------------------------------------------------------
__global__ __launch_bounds__(256) void qk_kernel(const float* __restrict__ Q,
                                                 const float* __restrict__ Km) {
    extern __shared__ float sm[];
    float* As = sm;                 // [64][AS_STR]  (d, s)
    float* Bs = sm + 64 * AS_STR;   // [64][BS_STR]  (d, t)
    const int tid = threadIdx.x;
    const int bh = blockIdx.z;
    const int s0 = blockIdx.y * 128, t0 = blockIdx.x * 64;
    const float* Qh = Q  + (size_t)bh * SDIM * DDIM;
    const float* Kh = Km + (size_t)bh * SDIM * DDIM;

#pragma unroll
    for (int j = 0; j < 8; j++) {
        int i = tid + j * 256;
        int r = i >> 4, c4 = i & 15;
        float4 q = __ldg((const float4*)(Qh + (size_t)(s0 + r) * DDIM) + c4);
        int d = c4 * 4;
        As[(d + 0) * AS_STR + r] = q.x * 0.125f;
        As[(d + 1) * AS_STR + r] = q.y * 0.125f;
        As[(d + 2) * AS_STR + r] = q.z * 0.125f;
        As[(d + 3) * AS_STR + r] = q.w * 0.125f;
    }
#pragma unroll
    for (int j = 0; j < 4; j++) {
        int i = tid + j * 256;
        int r = i >> 4, c4 = i & 15;
        float4 kv = __ldg((const float4*)(Kh + (size_t)(t0 + r) * DDIM) + c4);
        int d = c4 * 4;
        Bs[(d + 0) * BS_STR + r] = kv.x;
        Bs[(d + 1) * BS_STR + r] = kv.y;
        Bs[(d + 2) * BS_STR + r] = kv.z;
        Bs[(d + 3) * BS_STR + r] = kv.w;
    }
    __syncthreads();

    const int tx = tid & 15, ty = tid >> 4;
    const int c0 = tx * 4, r0 = ty * 8;

    ull acc[4][4];
#pragma unroll
    for (int j = 0; j < 4; j++)
#pragma unroll
        for (int p = 0; p < 4; p++) acc[j][p] = 0ull;

#pragma unroll 8
    for (int k = 0; k < 64; k++) {
        const ulonglong2* ap = (const ulonglong2*)(As + k * AS_STR + r0);
        ulonglong2 alo = ap[0];
        ulonglong2 ahi = ap[1];
        float4 b = *(const float4*)(Bs + k * BS_STR + c0);
        ull bd0, bd1, bd2, bd3;
        PACK_DUP(bd0, b.x); PACK_DUP(bd1, b.y);
        PACK_DUP(bd2, b.z); PACK_DUP(bd3, b.w);
        FMA2(acc[0][0], alo.x, bd0); FMA2(acc[0][1], alo.y, bd0);
        FMA2(acc[0][2], ahi.x, bd0); FMA2(acc[0][3], ahi.y, bd0);
        FMA2(acc[1][0], alo.x, bd1); FMA2(acc[1][1], alo.y, bd1);
        FMA2(acc[1][2], ahi.x, bd1); FMA2(acc[1][3], ahi.y, bd1);
        FMA2(acc[2][0], alo.x, bd2); FMA2(acc[2][1], alo.y, bd2);
        FMA2(acc[2][2], ahi.x, bd2); FMA2(acc[2][3], ahi.y, bd2);
        FMA2(acc[3][0], alo.x, bd3); FMA2(acc[3][1], alo.y, bd3);
        FMA2(acc[3][2], ahi.x, bd3); FMA2(acc[3][3], ahi.y, bd3);
    }

    float lo[4][4], hi[4][4];
#pragma unroll
    for (int j = 0; j < 4; j++)
#pragma unroll
        for (int p = 0; p < 4; p++) UNPACK2(lo[j][p], hi[j][p], acc[j][p]);

    float* out = g_dp + ((size_t)bh << 20);
#pragma unroll
    for (int i = 0; i < 8; i++) {
        int p = i >> 1;
        float4 o;
        if (i & 1) o = make_float4(hi[0][p], hi[1][p], hi[2][p], hi[3][p]);
        else       o = make_float4(lo[0][p], lo[1][p], lo[2][p], lo[3][p]);
        *(float4*)&out[(size_t)(s0 + r0 + i) * SDIM + t0 + c0] = o;
    }
}

// ---------------------------------------------------------------------------
// K2: fused conv(3x3,NF)+bias+leaky+linear+mask+softmax. R2 rows per block.
// Each thread: 4 CONSECUTIVE t (register tap reuse, vector mask/stores).
// ---------------------------------------------------------------------------
__global__ __launch_bounds__(256) void conv_softmax_kernel(
    const int* __restrict__ mask,
    const float* __restrict__ cw, const float* __restrict__ cb,
    const float* __restrict__ lw, const float* __restrict__ lb) {
    __shared__ float rows[R2 + 2][SDIM];
    __shared__ float red[9];
    const int tid = threadIdx.x;
    const int s0 = blockIdx.x * R2, bh = blockIdx.y;
    const float* dpb = g_dp + ((size_t)bh << 20);
    const int t0 = tid * 4;

#pragma unroll
    for (int j = 0; j < R2 + 2; j++) {
        int sr = s0 + j - 1;
        if (sr >= 0 && sr < SDIM) {
            const float4* src = (const float4*)(dpb + (size_t)sr * SDIM);
            ((float4*)rows[j])[tid] = __ldg(src + tid);
        } else {
            ((float4*)rows[j])[tid] = make_float4(0.f, 0.f, 0.f, 0.f);
        }
    }

    float w[NF][9], b_[NF], l_[NF];
#pragma unroll
    for (int f = 0; f < NF; f++) {
#pragma unroll
        for (int j = 0; j < 9; j++) w[f][j] = __ldg(&cw[f * 9 + j]);
        b_[f] = __ldg(&cb[f]);
        l_[f] = __ldg(&lw[f]);
    }
    const float lb0 = __ldg(lb);
    const int bb = bh >> 3;
    __syncthreads();

    for (int r = 0; r < R2; r++) {
        const int s = s0 + r;
        const int* mrow = mask + ((size_t)bb * SDIM + s) * SDIM;
        const int4 mv = __ldg((const int4*)(mrow + t0));

        // 6 taps per row: cL, c[0..3], cR
        float tap[3][6];
#pragma unroll
        for (int di = 0; di < 3; di++) {
            const float* rw = rows[r + di];
            float4 c = *(const float4*)&rw[t0];
            tap[di][0] = (t0 > 0) ? rw[t0 - 1] : 0.f;
            tap[di][1] = c.x; tap[di][2] = c.y; tap[di][3] = c.z; tap[di][4] = c.w;
            tap[di][5] = (t0 + 4 < SDIM) ? rw[t0 + 4] : 0.f;
        }

        float x[4];
#pragma unroll
        for (int p = 0; p < 4; p++) {
            float pre = lb0;
#pragma unroll
            for (int f = 0; f < NF; f++) {
                float c = b_[f];
#pragma unroll
                for (int di = 0; di < 3; di++) {
                    c += w[f][di * 3 + 0] * tap[di][p + 0];
                    c += w[f][di * 3 + 1] * tap[di][p + 1];
                    c += w[f][di * 3 + 2] * tap[di][p + 2];
                }
                pre += l_[f] * fmaxf(c, 0.01f * c);  // leaky_relu
            }
            x[p] = pre;
        }
        if (mv.x == 0) x[0] = -1e30f;
        if (mv.y == 0) x[1] = -1e30f;
        if (mv.z == 0) x[2] = -1e30f;
        if (mv.w == 0) x[3] = -1e30f;

        float m = fmaxf(fmaxf(x[0], x[1]), fmaxf(x[2], x[3]));
#pragma unroll
        for (int off = 16; off; off >>= 1)
            m = fmaxf(m, __shfl_xor_sync(0xffffffffu, m, off));
        if ((tid & 31) == 0) red[tid >> 5] = m;
        __syncthreads();
        if (tid == 0) {
            float mm = red[0];
#pragma unroll
            for (int i = 1; i < 8; i++) mm = fmaxf(mm, red[i]);
            red[8] = mm;
        }
        __syncthreads();
        m = red[8];
        __syncthreads();

        float e[4], ssum = 0.f;
#pragma unroll
        for (int p = 0; p < 4; p++) { e[p] = __expf(x[p] - m); ssum += e[p]; }
#pragma unroll
        for (int off = 16; off; off >>= 1)
            ssum += __shfl_xor_sync(0xffffffffu, ssum, off);
        if ((tid & 31) == 0) red[tid >> 5] = ssum;
        __syncthreads();
        if (tid == 0) {
            float sm = red[0];
#pragma unroll
            for (int i = 1; i < 8; i++) sm += red[i];
            red[8] = sm;
        }
        __syncthreads();
        const float inv = 1.0f / red[8];
        __syncthreads();

        float* arow = g_attn + ((size_t)bh << 20) + (size_t)s * SDIM;
        float4 o = make_float4(e[0] * inv, e[1] * inv, e[2] * inv, e[3] * inv);
        *(float4*)&arow[t0] = o;
    }
}

// ---------------------------------------------------------------------------
// K3a: AV partial GEMM, k-split, K1-style f32x2 tile.
// 128(s)x64(d) tile over a 256-wide k-range; 256 thr, 8s x 4d.
// grid = 8 s-tiles x 4 k-splits x 16 bh = 512 blocks.
// ---------------------------------------------------------------------------
__global__ __launch_bounds__(256) void av_partial(const float* __restrict__ V) {
    extern __shared__ float sm[];
    float* As = sm;                 // [64][AS_STR]  (k, s)  s 128-wide
    float* Bs = sm + 64 * AS_STR;   // [64][BS_STR]  (k, d)
    const int tid = threadIdx.x;
    const int bh = blockIdx.y;
    const int st = blockIdx.x & 7, ks = blockIdx.x >> 3;
    const int s0 = st * 128;
    const int kbase = ks * (SDIM / KSPL);
    const float* attn = g_attn + ((size_t)bh << 20);
    const float* Vh = V + (size_t)bh * SDIM * DDIM;
    const int tx = tid & 15, ty = tid >> 4;
    const int c0 = tx * 4, r0 = ty * 8;

    ull acc[4][4];
#pragma unroll
    for (int j = 0; j < 4; j++)
#pragma unroll
        for (int p = 0; p < 4; p++) acc[j][p] = 0ull;

    for (int kc = 0; kc < SDIM / KSPL; kc += 64) {
        const int k0 = kbase + kc;
        // attn tile 128s x 64k -> As[k][s] (transposed)
#pragma unroll
        for (int j = 0; j < 8; j++) {
            int i = tid + j * 256;
            int r = i >> 4, c4 = i & 15;
            float4 a = __ldg((const float4*)(attn + (size_t)(s0 + r) * SDIM + k0) + c4);
            int k = c4 * 4;
            As[(k + 0) * AS_STR + r] = a.x;
            As[(k + 1) * AS_STR + r] = a.y;
            As[(k + 2) * AS_STR + r] = a.z;
            As[(k + 3) * AS_STR + r] = a.w;
        }
        // V tile 64k x 64d -> Bs[k][d] (natural)
#pragma unroll
        for (int j = 0; j < 4; j++) {
            int i = tid + j * 256;
            int r = i >> 4, c4 = i & 15;
            float4 v = __ldg((const float4*)(Vh + (size_t)(k0 + r) * DDIM) + c4);
            *(float4*)&Bs[r * BS_STR + c4 * 4] = v;
        }
        __syncthreads();

#pragma unroll 8
        for (int k = 0; k < 64; k++) {
            const ulonglong2* ap = (const ulonglong2*)(As + k * AS_STR + r0);
            ulonglong2 alo = ap[0];
            ulonglong2 ahi = ap[1];
            float4 b = *(const float4*)(Bs + k * BS_STR + c0);
            ull bd0, bd1, bd2, bd3;
            PACK_DUP(bd0, b.x); PACK_DUP(bd1, b.y);
            PACK_DUP(bd2, b.z); PACK_DUP(bd3, b.w);
            FMA2(acc[0][0], alo.x, bd0); FMA2(acc[0][1], alo.y, bd0);
            FMA2(acc[0][2], ahi.x, bd0); FMA2(acc[0][3], ahi.y, bd0);
            FMA2(acc[1][0], alo.x, bd1); FMA2(acc[1][1], alo.y, bd1);
            FMA2(acc[1][2], ahi.x, bd1); FMA2(acc[1][3], ahi.y, bd1);
            FMA2(acc[2][0], alo.x, bd2); FMA2(acc[2][1], alo.y, bd2);
            FMA2(acc[2][2], ahi.x, bd2); FMA2(acc[2][3], ahi.y, bd2);
            FMA2(acc[3][0], alo.x, bd3); FMA2(acc[3][1], alo.y, bd3);
            FMA2(acc[3][2], ahi.x, bd3); FMA2(acc[3][3], ahi.y, bd3);
        }
        __syncthreads();
    }

    float lo[4][4], hi[4][4];
#pragma unroll
    for (int j = 0; j < 4; j++)
#pragma unroll
        for (int p = 0; p < 4; p++) UNPACK2(lo[j][p], hi[j][p], acc[j][p]);

    // partial[ks][bh][s][d] into g_dp
    float* pp = g_dp + (((size_t)ks * BH + bh) * SDIM + s0) * DDIM;
#pragma unroll
    for (int i = 0; i < 8; i++) {
        int p = i >> 1;
        float4 o;
        if (i & 1) o = make_float4(hi[0][p], hi[1][p], hi[2][p], hi[3][p]);
        else       o = make_float4(lo[0][p], lo[1][p], lo[2][p], lo[3][p]);
        *(float4*)&pp[(size_t)(r0 + i) * DDIM + c0] = o;
    }
}

// K3b: out = sum of KSPL partials. 2 outputs/thread -> 8 loads in flight.
__global__ __launch_bounds__(256) void av_reduce(float* __restrict__ out) {
    const size_t chunk = (size_t)BH * SDIM * DDIM / 4;        // 262144 float4s
    const size_t i0 = (size_t)blockIdx.x * 256 + threadIdx.x;
    const size_t i1 = i0 + chunk / 2;
    const float4* p = (const float4*)g_dp;
    float4 a0 = p[i0], a1 = p[i1];
#pragma unroll
    for (int k = 1; k < KSPL; k++) {
        float4 b0 = p[k * chunk + i0];
        float4 b1 = p[k * chunk + i1];
        a0.x += b0.x; a0.y += b0.y; a0.z += b0.z; a0.w += b0.w;
        a1.x += b1.x; a1.y += b1.y; a1.z += b1.z; a1.w += b1.w;
    }
    ((float4*)out)[i0] = a0;
    ((float4*)out)[i1] = a1;
}

extern "C" void kernel_launch(void* const* d_in, const int* in_sizes, int n_in,
                              void* d_out, int out_size) {
    const float* Q    = (const float*)d_in[0];
    const float* Kp   = (const float*)d_in[1];
    const float* V    = (const float*)d_in[2];
    const int*   mask = (const int*)d_in[3];
    const float* cw   = (const float*)d_in[4];
    const float* cb   = (const float*)d_in[5];
    const float* lw   = (const float*)d_in[6];
    const float* lb   = (const float*)d_in[7];
    float* out = (float*)d_out;

    const int gemm_smem = (64 * AS_STR + 64 * BS_STR) * sizeof(float);  // 51200 B
    static bool attr_set = false;
    if (!attr_set) {
        cudaFuncSetAttribute(qk_kernel, cudaFuncAttributeMaxDynamicSharedMemorySize, gemm_smem);
        cudaFuncSetAttribute(av_partial, cudaFuncAttributeMaxDynamicSharedMemorySize, gemm_smem);
        attr_set = true;
    }

    dim3 g1(SDIM / 64, SDIM / 128, BH);
    qk_kernel<<<g1, 256, gemm_smem>>>(Q, Kp);

    dim3 g2(SDIM / R2, BH);
    conv_softmax_kernel<<<g2, 256>>>(mask, cw, cb, lw, lb);

    dim3 g3((SDIM / 128) * KSPL, BH);
    av_partial<<<g3, 256, gemm_smem>>>(V);

    av_reduce<<<(BH * SDIM * DDIM / 4 / 2) / 256, 256>>>(out);
}

// round 17
// speedup vs baseline: 1.1797x; 1.1797x over previous
#include <cuda_runtime.h>
#include <cuda_bf16.h>
#include <cstdint>

#define SDIM 1024
#define DDIM 64
#define BH   16
#define NF   4
#define R2   4
#define KSPL 4

// Scratch
__device__ float g_dp[(size_t)BH * SDIM * SDIM];    // 64 MB; dp, then AV partials
__device__ float g_attn[(size_t)BH * SDIM * SDIM];  // 64 MB
__device__ __align__(16) __nv_bfloat16 g_qh[(size_t)BH * SDIM * DDIM];
__device__ __align__(16) __nv_bfloat16 g_ql[(size_t)BH * SDIM * DDIM];
__device__ __align__(16) __nv_bfloat16 g_kh[(size_t)BH * SDIM * DDIM];
__device__ __align__(16) __nv_bfloat16 g_kl[(size_t)BH * SDIM * DDIM];

__device__ __forceinline__ uint32_t smem_u32(const void* p) {
    uint32_t a;
    asm("{ .reg .u64 t; cvta.to.shared.u64 t, %1; cvt.u32.u64 %0, t; }" : "=r"(a) : "l"(p));
    return a;
}
#define LDMX4(r, addr)                                                        \
    asm volatile("ldmatrix.sync.aligned.m8n8.x4.shared.b16 {%0,%1,%2,%3}, [%4];" \
                 : "=r"((r)[0]), "=r"((r)[1]), "=r"((r)[2]), "=r"((r)[3]) : "r"(addr))
#define MMA16816(d, a, b0, b1)                                                \
    asm volatile("mma.sync.aligned.m16n8k16.row.col.f32.bf16.bf16.f32 "       \
                 "{%0,%1,%2,%3}, {%4,%5,%6,%7}, {%8,%9}, {%0,%1,%2,%3};"      \
                 : "+f"((d)[0]), "+f"((d)[1]), "+f"((d)[2]), "+f"((d)[3])     \
                 : "r"((a)[0]), "r"((a)[1]), "r"((a)[2]), "r"((a)[3]),        \
                   "r"(b0), "r"(b1))

// ---------------------------------------------------------------------------
// K0: split Q (scaled by 1/8) and K into bf16 hi+lo.
// ---------------------------------------------------------------------------
__global__ __launch_bounds__(256) void cvt_kernel(const float* __restrict__ Q,
                                                  const float* __restrict__ Km) {
    const size_t i0 = ((size_t)blockIdx.x * 256 + threadIdx.x) * 4;
    float4 q = *(const float4*)(Q + i0);
    float4 k = *(const float4*)(Km + i0);
    q.x *= 0.125f; q.y *= 0.125f; q.z *= 0.125f; q.w *= 0.125f;
    float qv[4] = {q.x, q.y, q.z, q.w};
    float kv[4] = {k.x, k.y, k.z, k.w};
    __nv_bfloat16 qh[4], ql[4], kh[4], kl[4];
#pragma unroll
    for (int j = 0; j < 4; j++) {
        qh[j] = __float2bfloat16(qv[j]);
        ql[j] = __float2bfloat16(qv[j] - __bfloat162float(qh[j]));
        kh[j] = __float2bfloat16(kv[j]);
        kl[j] = __float2bfloat16(kv[j] - __bfloat162float(kh[j]));
    }
    *(uint2*)(g_qh + i0) = *(uint2*)qh;
    *(uint2*)(g_ql + i0) = *(uint2*)ql;
    *(uint2*)(g_kh + i0) = *(uint2*)kh;
    *(uint2*)(g_kl + i0) = *(uint2*)kl;
}

// ---------------------------------------------------------------------------
// K1: dp tile 128(s) x 128(t) via HMMA (mma.sync bf16), split hi/lo, 3 passes.
// 8 warps, each 32(s) x 64(t). Shared tiles: 128 rows x 64 bf16, 144B stride.
// ---------------------------------------------------------------------------
#define TSTR 144                      // bytes per row in shared tile (72 bf16)
#define TILE_B (128 * TSTR)           // 18432 B per matrix
#define QK_SMEM (4 * TILE_B)          // 73728 B

__global__ __launch_bounds__(256) void qk_hmma() {
    extern __shared__ char smem[];
    char* Ah = smem;
    char* Al = smem + TILE_B;
    char* Bh = smem + 2 * TILE_B;
    char* Bl = smem + 3 * TILE_B;
    const int tid = threadIdx.x;
    const int wid = tid >> 5, lane = tid & 31;
    const int bh = blockIdx.z;
    const int s0 = blockIdx.y * 128, t0 = blockIdx.x * 128;

    // Load 4 tiles: 128 rows x 64 bf16 (128B) each, into 144B-stride shared.
    {
        const size_t qoff = ((size_t)bh * SDIM + s0) * DDIM;
        const size_t koff = ((size_t)bh * SDIM + t0) * DDIM;
        const uint4* srcs[4] = {(const uint4*)(g_qh + qoff), (const uint4*)(g_ql + qoff),
                                (const uint4*)(g_kh + koff), (const uint4*)(g_kl + koff)};
        char* dsts[4] = {Ah, Al, Bh, Bl};
#pragma unroll
        for (int m = 0; m < 4; m++) {
            const uint4* src = srcs[m];
            char* dst = dsts[m];
#pragma unroll
            for (int j = 0; j < 4; j++) {
                int i = tid + j * 256;          // 0..1023
                int r = i >> 3, c = i & 7;      // row, 16B chunk
                *(uint4*)(dst + r * TSTR + c * 16) = __ldg(src + (size_t)r * 8 + c);
            }
        }
    }
    __syncthreads();

    // Warp tiling: 4 (s) x 2 (t)
    const int sw = (wid >> 1) * 32;       // warp s offset within 128
    const int tw = (wid & 1) * 64;        // warp t offset within 128
    // ldmatrix per-lane offset: row = ((l>>3)&1)*8 + (l&7), 16B col = (l>>4)
    const int lrow = ((lane >> 3) & 1) * 8 + (lane & 7);
    const int loff = lrow * TSTR + (lane >> 4) * 16;

    const uint32_t aBase[3] = {smem_u32(Ah), smem_u32(Ah), smem_u32(Al)};
    const uint32_t bBase[3] = {smem_u32(Bh), smem_u32(Bl), smem_u32(Bh)};

    float d[2][8][4];
#pragma unroll
    for (int mi = 0; mi < 2; mi++)
#pragma unroll
        for (int nj = 0; nj < 8; nj++)
#pragma unroll
            for (int e = 0; e < 4; e++) d[mi][nj][e] = 0.f;

#pragma unroll
    for (int pass = 0; pass < 3; pass++) {
        const uint32_t ab = aBase[pass] + loff;
        const uint32_t bb = bBase[pass] + loff;
#pragma unroll
        for (int ks = 0; ks < 4; ks++) {
            uint32_t a[2][4];
#pragma unroll
            for (int mi = 0; mi < 2; mi++)
                LDMX4(a[mi], ab + (sw + mi * 16) * TSTR + ks * 32);
            uint32_t b[4][4];
#pragma unroll
            for (int ni = 0; ni < 4; ni++)
                LDMX4(b[ni], bb + (tw + ni * 16) * TSTR + ks * 32);
#pragma unroll
            for (int mi = 0; mi < 2; mi++)
#pragma unroll
                for (int nj = 0; nj < 8; nj++) {
                    // n-16-tile ni = nj>>1, patch p = nj&1: b0=b[ni][p], b1=b[ni][p+2]
                    MMA16816(d[mi][nj], a[mi], b[nj >> 1][nj & 1], b[nj >> 1][(nj & 1) + 2]);
                }
        }
    }

    // Epilogue: thread (g = lane>>2, tig = lane&3)
    const int g = lane >> 2, tig = lane & 3;
    float* outb = g_dp + ((size_t)bh << 20);
#pragma unroll
    for (int mi = 0; mi < 2; mi++) {
        const int row0 = s0 + sw + mi * 16 + g;
#pragma unroll
        for (int nj = 0; nj < 8; nj++) {
            const int col = t0 + tw + nj * 8 + tig * 2;
            *(float2*)&outb[(size_t)row0 * SDIM + col]       = make_float2(d[mi][nj][0], d[mi][nj][1]);
            *(float2*)&outb[(size_t)(row0 + 8) * SDIM + col] = make_float2(d[mi][nj][2], d[mi][nj][3]);
        }
    }
}

// ---------------------------------------------------------------------------
// K2: fused conv(3x3,NF)+bias+leaky+linear+mask+softmax. (R12 version)
// ---------------------------------------------------------------------------
__global__ __launch_bounds__(256) void conv_softmax_kernel(
    const int* __restrict__ mask,
    const float* __restrict__ cw, const float* __restrict__ cb,
    const float* __restrict__ lw, const float* __restrict__ lb) {
    __shared__ float rows[R2 + 2][SDIM];
    __shared__ float red[9];
    const int tid = threadIdx.x;
    const int s0 = blockIdx.x * R2, bh = blockIdx.y;
    const float* dpb = g_dp + ((size_t)bh << 20);

#pragma unroll
    for (int j = 0; j < R2 + 2; j++) {
        int sr = s0 + j - 1;
        if (sr >= 0 && sr < SDIM) {
            const float4* src = (const float4*)(dpb + (size_t)sr * SDIM);
            ((float4*)rows[j])[tid] = __ldg(src + tid);
        } else {
            ((float4*)rows[j])[tid] = make_float4(0.f, 0.f, 0.f, 0.f);
        }
    }

    float w[NF][9], b_[NF], l_[NF];
#pragma unroll
    for (int f = 0; f < NF; f++) {
#pragma unroll
        for (int j = 0; j < 9; j++) w[f][j] = __ldg(&cw[f * 9 + j]);
        b_[f] = __ldg(&cb[f]);
        l_[f] = __ldg(&lw[f]);
    }
    const float lb0 = __ldg(lb);
    const int bb = bh >> 3;
    __syncthreads();

    for (int r = 0; r < R2; r++) {
        const int s = s0 + r;
        const int* mrow = mask + ((size_t)bb * SDIM + s) * SDIM;

        float x[4];
#pragma unroll
        for (int q = 0; q < 4; q++) {
            int t = tid + q * 256;
            float v[9];
#pragma unroll
            for (int di = 0; di < 3; di++) {
#pragma unroll
                for (int dj = 0; dj < 3; dj++) {
                    int tt = t + dj - 1;
                    v[di * 3 + dj] = (tt >= 0 && tt < SDIM) ? rows[r + di][tt] : 0.f;
                }
            }
            float pre = lb0;
#pragma unroll
            for (int f = 0; f < NF; f++) {
                float c = b_[f];
#pragma unroll
                for (int j = 0; j < 9; j++) c += w[f][j] * v[j];
                pre += l_[f] * fmaxf(c, 0.01f * c);
            }
            if (__ldg(&mrow[t]) == 0) pre = -1e30f;
            x[q] = pre;
        }

        float m = fmaxf(fmaxf(x[0], x[1]), fmaxf(x[2], x[3]));
#pragma unroll
        for (int off = 16; off; off >>= 1)
            m = fmaxf(m, __shfl_xor_sync(0xffffffffu, m, off));
        if ((tid & 31) == 0) red[tid >> 5] = m;
        __syncthreads();
        if (tid == 0) {
            float mm = red[0];
#pragma unroll
            for (int i = 1; i < 8; i++) mm = fmaxf(mm, red[i]);
            red[8] = mm;
        }
        __syncthreads();
        m = red[8];
        __syncthreads();

        float e[4], ssum = 0.f;
#pragma unroll
        for (int q = 0; q < 4; q++) { e[q] = __expf(x[q] - m); ssum += e[q]; }
#pragma unroll
        for (int off = 16; off; off >>= 1)
            ssum += __shfl_xor_sync(0xffffffffu, ssum, off);
        if ((tid & 31) == 0) red[tid >> 5] = ssum;
        __syncthreads();
        if (tid == 0) {
            float sm = red[0];
#pragma unroll
            for (int i = 1; i < 8; i++) sm += red[i];
            red[8] = sm;
        }
        __syncthreads();
        const float inv = 1.0f / red[8];
        __syncthreads();

        float* arow = g_attn + ((size_t)bh << 20) + (size_t)s * SDIM;
#pragma unroll
        for (int q = 0; q < 4; q++) arow[tid + q * 256] = e[q] * inv;
    }
}

// ---------------------------------------------------------------------------
// K3a: AV partial GEMM, k-split (R12 version: 64x64 tile, 256 thr, KC=64).
// ---------------------------------------------------------------------------
__global__ __launch_bounds__(256) void av_partial(const float* __restrict__ V) {
    __shared__ float As[64][68];
    __shared__ float Bs[64][68];
    const int tid = threadIdx.x;
    const int bh = blockIdx.y;
    const int st = blockIdx.x & 15, ks = blockIdx.x >> 4;
    const int s0 = st * 64;
    const int kbase = ks * (SDIM / KSPL);
    const float* attn = g_attn + ((size_t)bh << 20);
    const float* Vh = V + (size_t)bh * SDIM * DDIM;
    const int tx = tid & 15, ty = tid >> 4;
    const int r0 = ty * 4, c0 = tx * 4;

    float acc[4][4] = {};
    for (int kc = 0; kc < SDIM / KSPL; kc += 64) {
        const int k0 = kbase + kc;
#pragma unroll
        for (int j = 0; j < 4; j++) {
            int i = tid + j * 256;
            int r = i >> 4, c4 = i & 15;
            float4 a = __ldg((const float4*)(attn + (size_t)(s0 + r) * SDIM + k0) + c4);
            *(float4*)&As[r][c4 * 4] = a;
        }
#pragma unroll
        for (int j = 0; j < 4; j++) {
            int i = tid + j * 256;
            int r = i >> 4, c4 = i & 15;
            float4 b = __ldg((const float4*)(Vh + (size_t)(k0 + r) * DDIM) + c4);
            *(float4*)&Bs[r][c4 * 4] = b;
        }
        __syncthreads();
#pragma unroll 16
        for (int k = 0; k < 64; k++) {
            float4 b = *(const float4*)&Bs[k][c0];
            float a0 = As[r0 + 0][k];
            float a1 = As[r0 + 1][k];
            float a2 = As[r0 + 2][k];
            float a3 = As[r0 + 3][k];
            acc[0][0] += a0 * b.x; acc[0][1] += a0 * b.y; acc[0][2] += a0 * b.z; acc[0][3] += a0 * b.w;
            acc[1][0] += a1 * b.x; acc[1][1] += a1 * b.y; acc[1][2] += a1 * b.z; acc[1][3] += a1 * b.w;
            acc[2][0] += a2 * b.x; acc[2][1] += a2 * b.y; acc[2][2] += a2 * b.z; acc[2][3] += a2 * b.w;
            acc[3][0] += a3 * b.x; acc[3][1] += a3 * b.y; acc[3][2] += a3 * b.z; acc[3][3] += a3 * b.w;
        }
        __syncthreads();
    }

    float* pp = g_dp + (((size_t)ks * BH + bh) * SDIM + s0) * DDIM;
#pragma unroll
    for (int i = 0; i < 4; i++) {
        float4 v = make_float4(acc[i][0], acc[i][1], acc[i][2], acc[i][3]);
        *(float4*)&pp[(size_t)(r0 + i) * DDIM + c0] = v;
    }
}

// K3b: out = sum of KSPL partials (R12 version).
__global__ __launch_bounds__(256) void av_reduce(float* __restrict__ out) {
    const size_t i = (size_t)blockIdx.x * 256 + threadIdx.x;
    const size_t chunk = (size_t)BH * SDIM * DDIM / 4;
    const float4* p = (const float4*)g_dp;
    float4 a = p[i];
#pragma unroll
    for (int k = 1; k < KSPL; k++) {
        float4 b = p[k * chunk + i];
        a.x += b.x; a.y += b.y; a.z += b.z; a.w += b.w;
    }
    ((float4*)out)[i] = a;
}

extern "C" void kernel_launch(void* const* d_in, const int* in_sizes, int n_in,
                              void* d_out, int out_size) {
    const float* Q    = (const float*)d_in[0];
    const float* Kp   = (const float*)d_in[1];
    const float* V    = (const float*)d_in[2];
    const int*   mask = (const int*)d_in[3];
    const float* cw   = (const float*)d_in[4];
    const float* cb   = (const float*)d_in[5];
    const float* lw   = (const float*)d_in[6];
    const float* lb   = (const float*)d_in[7];
    float* out = (float*)d_out;

    static bool attr_set = false;
    if (!attr_set) {
        cudaFuncSetAttribute(qk_hmma, cudaFuncAttributeMaxDynamicSharedMemorySize, QK_SMEM);
        attr_set = true;
    }

    cvt_kernel<<<(BH * SDIM * DDIM / 4) / 256, 256>>>(Q, Kp);

    dim3 g1(SDIM / 128, SDIM / 128, BH);
    qk_hmma<<<g1, 256, QK_SMEM>>>();

    dim3 g2(SDIM / R2, BH);
    conv_softmax_kernel<<<g2, 256>>>(mask, cw, cb, lw, lb);

    dim3 g3((SDIM / 64) * KSPL, BH);
    av_partial<<<g3, 256>>>(V);

    av_reduce<<<(BH * SDIM * DDIM / 4) / 256, 256>>>(out);
}